// round 1
// baseline (speedup 1.0000x reference)
#include <cuda_runtime.h>
#include <cuda_bf16.h>

// ---------------------------------------------------------------------------
// GNN: 4x GCNConv (3->16->32->48->64, relu) + global max pool + 2-layer MLP
// Strategy: build CSR (by destination) once per launch, then each conv is
//   hs = dinv[:,None] * (x @ W^T)            (dense, tiny)
//   out[v] = relu(dinv[v]*(sum_{u in N(v)} hs[u] + hs[v]) + b)   (gather, no atomics)
// All feature buffers fit in L2 (<= 25.6 MB), so gathers are L2 hits.
// ---------------------------------------------------------------------------

#define N_MAX 131072
#define E_MAX 3400000
#define G_MAX 512

__device__ int   g_deg[N_MAX];        // per-node incoming real-edge count
__device__ int   g_cursor[N_MAX];
__device__ int   g_off[N_MAX + 1];    // CSR offsets
__device__ int   g_src[E_MAX];        // CSR: source node per incoming edge
__device__ float g_dinv[N_MAX];
__device__ float g_bufA[N_MAX * 64];
__device__ float g_bufB[N_MAX * 64];
__device__ float g_pool[G_MAX * 64];

// ---------------------------- CSR construction ----------------------------

__global__ void init_kernel(int n, int gtot) {
    int i = blockIdx.x * blockDim.x + threadIdx.x;
    int tot = (n > gtot) ? n : gtot;
    for (; i < tot; i += gridDim.x * blockDim.x) {
        if (i < n) { g_deg[i] = 0; g_cursor[i] = 0; }
        if (i < gtot) g_pool[i] = 0.0f;   // relu outputs >= 0, so 0 is max-identity
    }
}

__global__ void hist_kernel(const int* __restrict__ col, int e) {
    int i = blockIdx.x * blockDim.x + threadIdx.x;
    if (i < e) atomicAdd(&g_deg[col[i]], 1);
}

// single-block exclusive scan over g_deg -> g_off
__global__ void scan_kernel(int n, int e) {
    __shared__ int sums[1024];
    int tid = threadIdx.x;
    int chunk = (n + 1023) / 1024;
    int start = tid * chunk;
    int end = start + chunk; if (end > n) end = n;
    int s = 0;
    for (int i = start; i < end; i++) s += g_deg[i];
    sums[tid] = s;
    __syncthreads();
    // Hillis-Steele inclusive scan
    for (int off = 1; off < 1024; off <<= 1) {
        int v = (tid >= off) ? sums[tid - off] : 0;
        __syncthreads();
        sums[tid] += v;
        __syncthreads();
    }
    int run = (tid > 0) ? sums[tid - 1] : 0;   // exclusive prefix of this chunk
    for (int i = start; i < end; i++) {
        g_off[i] = run;
        run += g_deg[i];
    }
    if (tid == 0) g_off[n] = e;
}

__global__ void fill_kernel(const int* __restrict__ row, const int* __restrict__ col, int e) {
    int i = blockIdx.x * blockDim.x + threadIdx.x;
    if (i < e) {
        int c = col[i];
        int p = g_off[c] + atomicAdd(&g_cursor[c], 1);
        g_src[p] = row[i];
    }
}

__global__ void dinv_kernel(int n) {
    int i = blockIdx.x * blockDim.x + threadIdx.x;
    if (i < n) g_dinv[i] = rsqrtf((float)(g_deg[i] + 1));  // +1 self loop
}

// ------------------------------- GCN layers -------------------------------

// hs[node][c] = dinv[node] * sum_k in[node][k] * W[c][k]
template <int CIN, int COUT>
__global__ void lin_kernel(const float* __restrict__ in, const float* __restrict__ W,
                           float* __restrict__ out, int n) {
    __shared__ float Ws[CIN * COUT];
    for (int i = threadIdx.x; i < CIN * COUT; i += blockDim.x) Ws[i] = W[i];
    __syncthreads();
    int idx = blockIdx.x * blockDim.x + threadIdx.x;
    if (idx >= n * COUT) return;
    int node = idx / COUT;
    int c = idx - node * COUT;
    const float* xr = in + node * CIN;
    float acc = 0.0f;
#pragma unroll
    for (int k = 0; k < CIN; k++) acc += xr[k] * Ws[c * CIN + k];
    out[idx] = g_dinv[node] * acc;
}

// out[v][c] = relu(dinv[v] * (hs[v][c] + sum_{u in N(v)} hs[u][c]) + b[c])
template <int COUT>
__global__ void agg_kernel(const float* __restrict__ hs, const float* __restrict__ b,
                           float* __restrict__ out, int n) {
    int warp = (blockIdx.x * blockDim.x + threadIdx.x) >> 5;
    int lane = threadIdx.x & 31;
    if (warp >= n) return;
    const int v = warp;
    const int c0 = lane;
    const int c1 = lane + 32;
    float acc0 = 0.0f, acc1 = 0.0f;
    if (c0 < COUT) acc0 = hs[v * COUT + c0];                  // self loop term
    if (COUT > 32 && c1 < COUT) acc1 = hs[v * COUT + c1];
    int j = g_off[v];
    const int jend = g_off[v + 1];
    for (; j + 4 <= jend; j += 4) {
        int u0 = __ldg(&g_src[j + 0]);
        int u1 = __ldg(&g_src[j + 1]);
        int u2 = __ldg(&g_src[j + 2]);
        int u3 = __ldg(&g_src[j + 3]);
        if (c0 < COUT)
            acc0 += hs[u0 * COUT + c0] + hs[u1 * COUT + c0] +
                    hs[u2 * COUT + c0] + hs[u3 * COUT + c0];
        if (COUT > 32 && c1 < COUT)
            acc1 += hs[u0 * COUT + c1] + hs[u1 * COUT + c1] +
                    hs[u2 * COUT + c1] + hs[u3 * COUT + c1];
    }
    for (; j < jend; j++) {
        int u = __ldg(&g_src[j]);
        if (c0 < COUT) acc0 += hs[u * COUT + c0];
        if (COUT > 32 && c1 < COUT) acc1 += hs[u * COUT + c1];
    }
    const float dv = g_dinv[v];
    if (c0 < COUT) out[v * COUT + c0] = fmaxf(dv * acc0 + __ldg(&b[c0]), 0.0f);
    if (COUT > 32 && c1 < COUT) out[v * COUT + c1] = fmaxf(dv * acc1 + __ldg(&b[c1]), 0.0f);
}

// --------------------------- pool + final MLP ------------------------------

// batch is sorted: per-block running max per channel, flush on segment change.
__global__ void pool_kernel(const float* __restrict__ h, const int* __restrict__ batch, int n) {
    const int NPB = 512;
    int c = threadIdx.x;   // 64 threads = 64 channels
    int start = blockIdx.x * NPB;
    if (start >= n) return;
    int end = start + NPB; if (end > n) end = n;
    int cur = batch[start];
    float m = 0.0f;
    for (int v = start; v < end; v++) {
        int gi = batch[v];
        if (gi != cur) {
            atomicMax((int*)&g_pool[cur * 64 + c], __float_as_int(m));
            cur = gi;
            m = 0.0f;
        }
        m = fmaxf(m, h[v * 64 + c]);
    }
    atomicMax((int*)&g_pool[cur * 64 + c], __float_as_int(m));
}

__global__ void mlp_kernel(const float* __restrict__ L1w, const float* __restrict__ L1b,
                           const float* __restrict__ L2w, const float* __restrict__ L2b,
                           float* __restrict__ out) {
    __shared__ float gs[64];
    __shared__ float t1[64];
    int gi = blockIdx.x;
    int t = threadIdx.x;   // 64 threads
    gs[t] = g_pool[gi * 64 + t];
    __syncthreads();
    float acc = L1b[t];
#pragma unroll
    for (int k = 0; k < 64; k++) acc += gs[k] * L1w[t * 64 + k];
    t1[t] = fmaxf(acc, 0.0f);
    __syncthreads();
    if (t < 10) {
        float a = L2b[t];
#pragma unroll
        for (int k = 0; k < 64; k++) a += t1[k] * L2w[t * 64 + k];
        out[gi * 10 + t] = a;
    }
}

// ------------------------------- launcher ----------------------------------

extern "C" void kernel_launch(void* const* d_in, const int* in_sizes, int n_in,
                              void* d_out, int out_size) {
    const float* x    = (const float*)d_in[0];
    const int*   ei   = (const int*)d_in[1];
    const int*   batch= (const int*)d_in[2];
    // d_in[3] = num_graphs (scalar) — derived from out_size instead
    const float* W1 = (const float*)d_in[4];
    const float* b1 = (const float*)d_in[5];
    const float* W2 = (const float*)d_in[6];
    const float* b2 = (const float*)d_in[7];
    const float* W3 = (const float*)d_in[8];
    const float* b3 = (const float*)d_in[9];
    const float* W4 = (const float*)d_in[10];
    const float* b4 = (const float*)d_in[11];
    const float* L1w = (const float*)d_in[12];
    const float* L1b = (const float*)d_in[13];
    const float* L2w = (const float*)d_in[14];
    const float* L2b = (const float*)d_in[15];
    float* out = (float*)d_out;

    const int n = in_sizes[0] / 3;
    const int e = in_sizes[1] / 2;
    const int G = out_size / 10;

    const int* row = ei;
    const int* col = ei + e;

    float* bufA; cudaGetSymbolAddress((void**)&bufA, g_bufA);
    float* bufB; cudaGetSymbolAddress((void**)&bufB, g_bufB);

    // ---- CSR build ----
    {
        int tot = (n > G * 64) ? n : G * 64;
        init_kernel<<<(tot + 255) / 256, 256>>>(n, G * 64);
        hist_kernel<<<(e + 255) / 256, 256>>>(col, e);
        scan_kernel<<<1, 1024>>>(n, e);
        fill_kernel<<<(e + 255) / 256, 256>>>(row, col, e);
        dinv_kernel<<<(n + 255) / 256, 256>>>(n);
    }

    const int WPB = 8;                       // warps per block in agg
    const int agg_grid = (n + WPB - 1) / WPB;

    // ---- layer 1: 3 -> 16 ----
    lin_kernel<3, 16><<<(n * 16 + 255) / 256, 256>>>(x, W1, bufA, n);
    agg_kernel<16><<<agg_grid, WPB * 32>>>(bufA, b1, bufB, n);
    // ---- layer 2: 16 -> 32 ----
    lin_kernel<16, 32><<<(n * 32 + 255) / 256, 256>>>(bufB, W2, bufA, n);
    agg_kernel<32><<<agg_grid, WPB * 32>>>(bufA, b2, bufB, n);
    // ---- layer 3: 32 -> 48 ----
    lin_kernel<32, 48><<<(n * 48 + 255) / 256, 256>>>(bufB, W3, bufA, n);
    agg_kernel<48><<<agg_grid, WPB * 32>>>(bufA, b3, bufB, n);
    // ---- layer 4: 48 -> 64 ----
    lin_kernel<48, 64><<<(n * 64 + 255) / 256, 256>>>(bufB, W4, bufA, n);
    agg_kernel<64><<<agg_grid, WPB * 32>>>(bufA, b4, bufB, n);

    // ---- pool + MLP ----
    pool_kernel<<<(n + 511) / 512, 64>>>(bufB, batch, n);
    mlp_kernel<<<G, 64>>>(L1w, L1b, L2w, L2b, out);
}

// round 2
// speedup vs baseline: 1.3494x; 1.3494x over previous
#include <cuda_runtime.h>
#include <cuda_bf16.h>

// ---------------------------------------------------------------------------
// GNN: 4x GCNConv (3->16->32->48->64, relu) + global max pool + 2-layer MLP
// Round-2 strategy: aggregate-then-transform (A(XW) == (AX)W), so gathers run
// on the *input* width of each layer (3/16/32/48 instead of 16/32/48/64).
// One fused kernel per layer: CSR gather (float2 channel-parallel) -> tiny
// matmul from shared (W transposed, conflict-free) -> relu+bias -> output
// pre-scaled by dinv for the next layer's gather.
// ---------------------------------------------------------------------------

#define N_MAX 131072
#define E_MAX 3400000
#define G_MAX 512

__device__ int    g_deg[N_MAX];
__device__ int    g_cursor[N_MAX];
__device__ int    g_off[N_MAX + 1];
__device__ int    g_src[E_MAX];
__device__ float  g_dinv[N_MAX];
__device__ float4 g_s0[N_MAX];            // layer-1 input, dinv-scaled, padded to 4
__device__ float  g_bufA[N_MAX * 64];
__device__ float  g_bufB[N_MAX * 64];
__device__ float  g_pool[G_MAX * 64];

// ---------------------------- CSR construction ----------------------------

__global__ void init_kernel(int n, int gtot) {
    int i = blockIdx.x * blockDim.x + threadIdx.x;
    int tot = (n > gtot) ? n : gtot;
    for (; i < tot; i += gridDim.x * blockDim.x) {
        if (i < n) { g_deg[i] = 0; g_cursor[i] = 0; }
        if (i < gtot) g_pool[i] = 0.0f;   // relu outputs >= 0 -> 0 is max-identity
    }
}

__global__ void hist_kernel(const int* __restrict__ col, int e) {
    int i = blockIdx.x * blockDim.x + threadIdx.x;
    if (i < e) atomicAdd(&g_deg[col[i]], 1);
}

// single-block exclusive scan over g_deg -> g_off
__global__ void scan_kernel(int n, int e) {
    __shared__ int sums[1024];
    int tid = threadIdx.x;
    int chunk = (n + 1023) / 1024;
    int start = tid * chunk;
    int end = start + chunk; if (end > n) end = n;
    int s = 0;
    for (int i = start; i < end; i++) s += g_deg[i];
    sums[tid] = s;
    __syncthreads();
    for (int off = 1; off < 1024; off <<= 1) {
        int v = (tid >= off) ? sums[tid - off] : 0;
        __syncthreads();
        sums[tid] += v;
        __syncthreads();
    }
    int run = (tid > 0) ? sums[tid - 1] : 0;
    for (int i = start; i < end; i++) {
        g_off[i] = run;
        run += g_deg[i];
    }
    if (tid == 0) g_off[n] = e;
}

__global__ void fill_kernel(const int* __restrict__ row, const int* __restrict__ col, int e) {
    int i = blockIdx.x * blockDim.x + threadIdx.x;
    if (i < e) {
        int c = col[i];
        int p = g_off[c] + atomicAdd(&g_cursor[c], 1);
        g_src[p] = row[i];
    }
}

// dinv + build dinv-scaled padded layer-1 input
__global__ void dinv_prep_kernel(const float* __restrict__ x, int n) {
    int i = blockIdx.x * blockDim.x + threadIdx.x;
    if (i < n) {
        float dv = rsqrtf((float)(g_deg[i] + 1));  // +1 self loop
        g_dinv[i] = dv;
        g_s0[i] = make_float4(dv * x[3*i], dv * x[3*i+1], dv * x[3*i+2], 0.0f);
    }
}

// ------------------------------- GCN layers -------------------------------

// Layer 1 (Cin=3 pad 4 -> Cout=16): edge-parallel gather of float4 rows,
// warp shfl_xor reduce, then per-lane matmul. Output pre-scaled by dinv.
__global__ void layer1_kernel(const float* __restrict__ W, const float* __restrict__ b,
                              float* __restrict__ out, int n) {
    __shared__ float Ws[48];
    __shared__ float bs[16];
    if (threadIdx.x < 48) Ws[threadIdx.x] = W[threadIdx.x];
    if (threadIdx.x < 16) bs[threadIdx.x] = b[threadIdx.x];
    __syncthreads();
    int warp = threadIdx.x >> 5, lane = threadIdx.x & 31;
    int v = blockIdx.x * 8 + warp;
    if (v >= n) return;
    float ax = 0.0f, ay = 0.0f, az = 0.0f;
    int jend = g_off[v + 1];
    for (int j = g_off[v] + lane; j < jend; j += 32) {
        float4 a = g_s0[__ldg(&g_src[j])];
        ax += a.x; ay += a.y; az += a.z;
    }
    if (lane == 0) {
        float4 a = g_s0[v];   // self loop
        ax += a.x; ay += a.y; az += a.z;
    }
#pragma unroll
    for (int o = 16; o; o >>= 1) {
        ax += __shfl_xor_sync(0xffffffffu, ax, o);
        ay += __shfl_xor_sync(0xffffffffu, ay, o);
        az += __shfl_xor_sync(0xffffffffu, az, o);
    }
    float dv = g_dinv[v];
    ax *= dv; ay *= dv; az *= dv;
    if (lane < 16) {
        float r = bs[lane] + ax * Ws[lane*3] + ay * Ws[lane*3+1] + az * Ws[lane*3+2];
        out[v * 16 + lane] = dv * fmaxf(r, 0.0f);   // pre-scale for next layer
    }
}

// Layers 2-4: channel-parallel float2 gather + shared-mem matmul.
// s rows are already dinv[u]-scaled; agg gets dinv[v]; out = relu(agg@W^T + b),
// optionally pre-scaled by dinv for the next layer.
template <int CIN, int COUT, bool SCALE>
__global__ void layer_kernel(const float2* __restrict__ s, const float* __restrict__ W,
                             const float* __restrict__ b, float* __restrict__ out, int n) {
    constexpr int HC = CIN / 2;
    __shared__ float Wt[CIN * COUT];    // transposed: Wt[k*COUT + c]
    __shared__ float bs[COUT];
    __shared__ float aggS[8][CIN];
    for (int i = threadIdx.x; i < CIN * COUT; i += blockDim.x) {
        int c = i / CIN, k = i - c * CIN;
        Wt[k * COUT + c] = W[i];
    }
    if (threadIdx.x < COUT) bs[threadIdx.x] = b[threadIdx.x];
    __syncthreads();
    int warp = threadIdx.x >> 5, lane = threadIdx.x & 31;
    int v = blockIdx.x * 8 + warp;
    if (v >= n) return;
    float dv = g_dinv[v];
    if (lane < HC) {
        float2 acc = s[v * HC + lane];              // self loop
        int j = g_off[v];
        const int jend = g_off[v + 1];
        for (; j + 4 <= jend; j += 4) {
            int u0 = __ldg(&g_src[j + 0]);
            int u1 = __ldg(&g_src[j + 1]);
            int u2 = __ldg(&g_src[j + 2]);
            int u3 = __ldg(&g_src[j + 3]);
            float2 a0 = s[u0 * HC + lane];
            float2 a1 = s[u1 * HC + lane];
            float2 a2 = s[u2 * HC + lane];
            float2 a3 = s[u3 * HC + lane];
            acc.x += (a0.x + a1.x) + (a2.x + a3.x);
            acc.y += (a0.y + a1.y) + (a2.y + a3.y);
        }
        for (; j < jend; j++) {
            float2 a = s[__ldg(&g_src[j]) * HC + lane];
            acc.x += a.x; acc.y += a.y;
        }
        aggS[warp][2 * lane]     = acc.x * dv;
        aggS[warp][2 * lane + 1] = acc.y * dv;
    }
    __syncwarp();
    float a0 = bs[lane];
    float a1 = (COUT > 32 && lane + 32 < COUT) ? bs[lane + 32] : 0.0f;
#pragma unroll
    for (int k = 0; k < CIN; k++) {
        float av = aggS[warp][k];                   // broadcast, conflict-free
        a0 += av * Wt[k * COUT + lane];
        if (COUT > 32 && lane + 32 < COUT) a1 += av * Wt[k * COUT + lane + 32];
    }
    a0 = fmaxf(a0, 0.0f);
    out[v * COUT + lane] = SCALE ? dv * a0 : a0;
    if (COUT > 32 && lane + 32 < COUT) {
        a1 = fmaxf(a1, 0.0f);
        out[v * COUT + lane + 32] = SCALE ? dv * a1 : a1;
    }
}

// --------------------------- pool + final MLP ------------------------------

__global__ void pool_kernel(const float* __restrict__ h, const int* __restrict__ batch, int n) {
    const int NPB = 512;
    int c = threadIdx.x;   // 64 threads = 64 channels
    int start = blockIdx.x * NPB;
    if (start >= n) return;
    int end = start + NPB; if (end > n) end = n;
    int cur = batch[start];
    float m = 0.0f;
    for (int v = start; v < end; v++) {
        int gi = batch[v];
        if (gi != cur) {
            atomicMax((int*)&g_pool[cur * 64 + c], __float_as_int(m));
            cur = gi;
            m = 0.0f;
        }
        m = fmaxf(m, h[v * 64 + c]);
    }
    atomicMax((int*)&g_pool[cur * 64 + c], __float_as_int(m));
}

__global__ void mlp_kernel(const float* __restrict__ L1w, const float* __restrict__ L1b,
                           const float* __restrict__ L2w, const float* __restrict__ L2b,
                           float* __restrict__ out) {
    __shared__ float gs[64];
    __shared__ float t1[64];
    int gi = blockIdx.x;
    int t = threadIdx.x;   // 64 threads
    gs[t] = g_pool[gi * 64 + t];
    __syncthreads();
    float acc = L1b[t];
#pragma unroll
    for (int k = 0; k < 64; k++) acc += gs[k] * L1w[t * 64 + k];
    t1[t] = fmaxf(acc, 0.0f);
    __syncthreads();
    if (t < 10) {
        float a = L2b[t];
#pragma unroll
        for (int k = 0; k < 64; k++) a += t1[k] * L2w[t * 64 + k];
        out[gi * 10 + t] = a;
    }
}

// ------------------------------- launcher ----------------------------------

extern "C" void kernel_launch(void* const* d_in, const int* in_sizes, int n_in,
                              void* d_out, int out_size) {
    const float* x     = (const float*)d_in[0];
    const int*   ei    = (const int*)d_in[1];
    const int*   batch = (const int*)d_in[2];
    const float* W1 = (const float*)d_in[4];
    const float* b1 = (const float*)d_in[5];
    const float* W2 = (const float*)d_in[6];
    const float* b2 = (const float*)d_in[7];
    const float* W3 = (const float*)d_in[8];
    const float* b3 = (const float*)d_in[9];
    const float* W4 = (const float*)d_in[10];
    const float* b4 = (const float*)d_in[11];
    const float* L1w = (const float*)d_in[12];
    const float* L1b = (const float*)d_in[13];
    const float* L2w = (const float*)d_in[14];
    const float* L2b = (const float*)d_in[15];
    float* out = (float*)d_out;

    const int n = in_sizes[0] / 3;
    const int e = in_sizes[1] / 2;
    const int G = out_size / 10;

    const int* row = ei;
    const int* col = ei + e;

    float* bufA; cudaGetSymbolAddress((void**)&bufA, g_bufA);
    float* bufB; cudaGetSymbolAddress((void**)&bufB, g_bufB);

    // ---- CSR build + prep ----
    {
        int tot = (n > G * 64) ? n : G * 64;
        init_kernel<<<(tot + 255) / 256, 256>>>(n, G * 64);
        hist_kernel<<<(e + 255) / 256, 256>>>(col, e);
        scan_kernel<<<1, 1024>>>(n, e);
        fill_kernel<<<(e + 255) / 256, 256>>>(row, col, e);
        dinv_prep_kernel<<<(n + 255) / 256, 256>>>(x, n);
    }

    const int agg_grid = (n + 7) / 8;   // 8 warps/block, warp per node

    // ---- fused layers: gather(Cin) -> W -> relu -> (dinv-prescale) ----
    layer1_kernel<<<agg_grid, 256>>>(W1, b1, bufB, n);                                  // 3->16
    layer_kernel<16, 32, true ><<<agg_grid, 256>>>((const float2*)bufB, W2, b2, bufA, n); // 16->32
    layer_kernel<32, 48, true ><<<agg_grid, 256>>>((const float2*)bufA, W3, b3, bufB, n); // 32->48
    layer_kernel<48, 64, false><<<agg_grid, 256>>>((const float2*)bufB, W4, b4, bufA, n); // 48->64

    // ---- pool + MLP ----
    pool_kernel<<<(n + 511) / 512, 64>>>(bufA, batch, n);
    mlp_kernel<<<G, 64>>>(L1w, L1b, L2w, L2b, out);
}

// round 3
// speedup vs baseline: 1.8033x; 1.3364x over previous
#include <cuda_runtime.h>
#include <cuda_fp16.h>
#include <cuda_bf16.h>

// ---------------------------------------------------------------------------
// GNN: 4x GCNConv (3->16->32->48->64, relu) + global max pool + 2-layer MLP
// Round-3: fp16 feature buffers (halves L1tex wavefronts per edge gather),
// all-lane edge-group gathers (uint2/half4 loads), two-level parallel scan.
// Aggregate-then-transform; features pre-scaled by dinv of their source node.
// ---------------------------------------------------------------------------

#define N_MAX 131072
#define E_MAX 3400000
#define G_MAX 512

__device__ int    g_deg[N_MAX];
__device__ int    g_cursor[N_MAX];
__device__ int    g_off[N_MAX + 1];
__device__ int    g_src[E_MAX];
__device__ int    g_bsum[256];
__device__ int    g_boff[256];
__device__ float  g_dinv[N_MAX];
__device__ uint2  g_s0[N_MAX];            // layer-1 input as half4, dinv-scaled
__device__ uint2  g_hA[N_MAX * 16];       // half feature buffer (64 ch max)
__device__ uint2  g_hB[N_MAX * 16];       // half feature buffer
__device__ float  g_bufA[N_MAX * 64];     // fp32 final features for pool
__device__ float  g_pool[G_MAX * 64];

// ---------------------------- CSR construction ----------------------------

__global__ void init_kernel(int n, int gtot) {
    int i = blockIdx.x * blockDim.x + threadIdx.x;
    int tot = (n > gtot) ? n : gtot;
    for (; i < tot; i += gridDim.x * blockDim.x) {
        if (i < n) { g_deg[i] = 0; g_cursor[i] = 0; }
        if (i < gtot) g_pool[i] = 0.0f;   // relu outputs >= 0 -> 0 is max-identity
    }
}

__global__ void hist_kernel(const int* __restrict__ col, int e) {
    int i = blockIdx.x * blockDim.x + threadIdx.x;
    if (i < e) atomicAdd(&g_deg[col[i]], 1);
}

// two-level exclusive scan of g_deg -> g_off
__global__ void scan_local(int n) {
    __shared__ int sm[256];
    int b = blockIdx.x, t = threadIdx.x;
    int i0 = b * 512 + 2 * t, i1 = i0 + 1;
    int v0 = (i0 < n) ? g_deg[i0] : 0;
    int v1 = (i1 < n) ? g_deg[i1] : 0;
    sm[t] = v0 + v1;
    __syncthreads();
    for (int o = 1; o < 256; o <<= 1) {
        int x = (t >= o) ? sm[t - o] : 0;
        __syncthreads();
        sm[t] += x;
        __syncthreads();
    }
    int ex = (t > 0) ? sm[t - 1] : 0;
    if (i0 < n) g_off[i0] = ex;
    if (i1 < n) g_off[i1] = ex + v0;
    if (t == 255) g_bsum[b] = sm[255];
}

__global__ void scan_spine(int nblk) {
    __shared__ int sm[256];
    int t = threadIdx.x;
    sm[t] = (t < nblk) ? g_bsum[t] : 0;
    __syncthreads();
    for (int o = 1; o < 256; o <<= 1) {
        int x = (t >= o) ? sm[t - o] : 0;
        __syncthreads();
        sm[t] += x;
        __syncthreads();
    }
    g_boff[t] = (t > 0) ? sm[t - 1] : 0;
}

__global__ void scan_add(int n, int e) {
    int i = blockIdx.x * blockDim.x + threadIdx.x;
    if (i < n) g_off[i] += g_boff[i >> 9];
    if (i == 0) g_off[n] = e;
}

__global__ void fill_kernel(const int* __restrict__ row, const int* __restrict__ col, int e) {
    int i = blockIdx.x * blockDim.x + threadIdx.x;
    if (i < e) {
        int c = col[i];
        int p = g_off[c] + atomicAdd(&g_cursor[c], 1);
        g_src[p] = row[i];
    }
}

// dinv + build dinv-scaled half4 layer-1 input
__global__ void dinv_prep_kernel(const float* __restrict__ x, int n) {
    int i = blockIdx.x * blockDim.x + threadIdx.x;
    if (i < n) {
        float dv = rsqrtf((float)(g_deg[i] + 1));  // +1 self loop
        g_dinv[i] = dv;
        __half2 lo = __floats2half2_rn(dv * x[3*i],   dv * x[3*i+1]);
        __half2 hi = __floats2half2_rn(dv * x[3*i+2], 0.0f);
        uint2 w;
        w.x = *reinterpret_cast<unsigned*>(&lo);
        w.y = *reinterpret_cast<unsigned*>(&hi);
        g_s0[i] = w;
    }
}

// ------------------------------- GCN layers -------------------------------

// Layer 1 (Cin=3 pad 4 -> Cout=16): edge-parallel half4 gather, shfl reduce.
__global__ void layer1_kernel(const float* __restrict__ W, const float* __restrict__ b,
                              int n) {
    __shared__ float Ws[48];
    __shared__ float bs[16];
    if (threadIdx.x < 48) Ws[threadIdx.x] = W[threadIdx.x];
    if (threadIdx.x < 16) bs[threadIdx.x] = b[threadIdx.x];
    __syncthreads();
    int warp = threadIdx.x >> 5, lane = threadIdx.x & 31;
    int v = blockIdx.x * 8 + warp;
    if (v >= n) return;
    float ax = 0.0f, ay = 0.0f, az = 0.0f;
    int jend = g_off[v + 1];
    for (int j = g_off[v] + lane; j < jend; j += 32) {
        uint2 w = g_s0[__ldg(&g_src[j])];
        float2 f0 = __half22float2(*reinterpret_cast<__half2*>(&w.x));
        float2 f1 = __half22float2(*reinterpret_cast<__half2*>(&w.y));
        ax += f0.x; ay += f0.y; az += f1.x;
    }
    if (lane == 0) {
        uint2 w = g_s0[v];   // self loop
        float2 f0 = __half22float2(*reinterpret_cast<__half2*>(&w.x));
        float2 f1 = __half22float2(*reinterpret_cast<__half2*>(&w.y));
        ax += f0.x; ay += f0.y; az += f1.x;
    }
#pragma unroll
    for (int o = 16; o; o >>= 1) {
        ax += __shfl_xor_sync(0xffffffffu, ax, o);
        ay += __shfl_xor_sync(0xffffffffu, ay, o);
        az += __shfl_xor_sync(0xffffffffu, az, o);
    }
    float dv = g_dinv[v];
    ax *= dv; ay *= dv; az *= dv;
    if (lane < 16) {
        float r = bs[lane] + ax * Ws[lane*3] + ay * Ws[lane*3+1] + az * Ws[lane*3+2];
        __half* outh = reinterpret_cast<__half*>(g_hA);
        outh[v * 16 + lane] = __float2half_rn(dv * fmaxf(r, 0.0f));  // pre-scale
    }
}

// Layers 2-4: edge-group half4 gather (all lanes busy) + shared-mem matmul.
// QC = CIN/4 lanes per edge row, EG edge groups per warp.
template <int CIN, int COUT, bool SCALE, bool HALFOUT>
__global__ void layer_kernel(const uint2* __restrict__ s, __half* __restrict__ outh,
                             float* __restrict__ outf,
                             const float* __restrict__ W, const float* __restrict__ b,
                             int n) {
    constexpr int QC = CIN / 4;
    constexpr int EG = 32 / QC;
    constexpr int ACT = QC * EG;
    __shared__ float Wt[CIN * COUT];     // transposed: Wt[k*COUT + c]
    __shared__ float bs[COUT];
    __shared__ float aggS[8][CIN];
    for (int i = threadIdx.x; i < CIN * COUT; i += blockDim.x) {
        int c = i / CIN, k = i - c * CIN;
        Wt[k * COUT + c] = W[i];
    }
    if (threadIdx.x < COUT) bs[threadIdx.x] = b[threadIdx.x];
    __syncthreads();
    int warp = threadIdx.x >> 5, lane = threadIdx.x & 31;
    int v = blockIdx.x * 8 + warp;
    if (v >= n) return;
    const float dv = g_dinv[v];
    const int eg = lane / QC;
    const int q  = lane - eg * QC;

    float a0 = 0.0f, a1 = 0.0f, a2 = 0.0f, a3 = 0.0f;
    const int jend = g_off[v + 1];
    int j = (lane < ACT) ? (g_off[v] + eg) : jend;
    if (lane < ACT && eg == 0) {
        uint2 w = s[v * QC + q];         // self loop
        float2 f0 = __half22float2(*reinterpret_cast<__half2*>(&w.x));
        float2 f1 = __half22float2(*reinterpret_cast<__half2*>(&w.y));
        a0 += f0.x; a1 += f0.y; a2 += f1.x; a3 += f1.y;
    }
    for (; j + EG < jend; j += 2 * EG) {
        int u0 = __ldg(&g_src[j]);
        int u1 = __ldg(&g_src[j + EG]);
        uint2 w0 = s[u0 * QC + q];
        uint2 w1 = s[u1 * QC + q];
        float2 p0 = __half22float2(*reinterpret_cast<__half2*>(&w0.x));
        float2 p1 = __half22float2(*reinterpret_cast<__half2*>(&w0.y));
        float2 p2 = __half22float2(*reinterpret_cast<__half2*>(&w1.x));
        float2 p3 = __half22float2(*reinterpret_cast<__half2*>(&w1.y));
        a0 += p0.x + p2.x; a1 += p0.y + p2.y;
        a2 += p1.x + p3.x; a3 += p1.y + p3.y;
    }
    if (j < jend) {
        int u = __ldg(&g_src[j]);
        uint2 w = s[u * QC + q];
        float2 p0 = __half22float2(*reinterpret_cast<__half2*>(&w.x));
        float2 p1 = __half22float2(*reinterpret_cast<__half2*>(&w.y));
        a0 += p0.x; a1 += p0.y; a2 += p1.x; a3 += p1.y;
    }
    // reduce across edge groups
    if constexpr ((QC & (QC - 1)) == 0) {
#pragma unroll
        for (int o = QC; o < 32; o <<= 1) {
            a0 += __shfl_xor_sync(0xffffffffu, a0, o);
            a1 += __shfl_xor_sync(0xffffffffu, a1, o);
            a2 += __shfl_xor_sync(0xffffffffu, a2, o);
            a3 += __shfl_xor_sync(0xffffffffu, a3, o);
        }
    } else {   // QC=12, EG=2
        a0 += __shfl_down_sync(0xffffffffu, a0, 12);
        a1 += __shfl_down_sync(0xffffffffu, a1, 12);
        a2 += __shfl_down_sync(0xffffffffu, a2, 12);
        a3 += __shfl_down_sync(0xffffffffu, a3, 12);
    }
    if (lane < QC) {
        aggS[warp][q * 4 + 0] = a0 * dv;
        aggS[warp][q * 4 + 1] = a1 * dv;
        aggS[warp][q * 4 + 2] = a2 * dv;
        aggS[warp][q * 4 + 3] = a3 * dv;
    }
    __syncwarp();
    float r0 = bs[lane];
    float r1 = (COUT > 32 && lane + 32 < COUT) ? bs[lane + 32] : 0.0f;
#pragma unroll
    for (int k = 0; k < CIN; k++) {
        float av = aggS[warp][k];                    // broadcast
        r0 += av * Wt[k * COUT + lane];
        if (COUT > 32 && lane + 32 < COUT) r1 += av * Wt[k * COUT + lane + 32];
    }
    r0 = fmaxf(r0, 0.0f);
    if (SCALE) r0 *= dv;
    if (HALFOUT) outh[v * COUT + lane] = __float2half_rn(r0);
    else         outf[v * COUT + lane] = r0;
    if (COUT > 32 && lane + 32 < COUT) {
        r1 = fmaxf(r1, 0.0f);
        if (SCALE) r1 *= dv;
        if (HALFOUT) outh[v * COUT + lane + 32] = __float2half_rn(r1);
        else         outf[v * COUT + lane + 32] = r1;
    }
}

// --------------------------- pool + final MLP ------------------------------

__global__ void pool_kernel(const float* __restrict__ h, const int* __restrict__ batch, int n) {
    const int NPB = 512;
    int c = threadIdx.x;   // 64 threads = 64 channels
    int start = blockIdx.x * NPB;
    if (start >= n) return;
    int end = start + NPB; if (end > n) end = n;
    int cur = batch[start];
    float m = 0.0f;
    for (int v = start; v < end; v++) {
        int gi = batch[v];
        if (gi != cur) {
            atomicMax((int*)&g_pool[cur * 64 + c], __float_as_int(m));
            cur = gi;
            m = 0.0f;
        }
        m = fmaxf(m, h[v * 64 + c]);
    }
    atomicMax((int*)&g_pool[cur * 64 + c], __float_as_int(m));
}

__global__ void mlp_kernel(const float* __restrict__ L1w, const float* __restrict__ L1b,
                           const float* __restrict__ L2w, const float* __restrict__ L2b,
                           float* __restrict__ out) {
    __shared__ float gs[64];
    __shared__ float t1[64];
    int gi = blockIdx.x;
    int t = threadIdx.x;   // 64 threads
    gs[t] = g_pool[gi * 64 + t];
    __syncthreads();
    float acc = L1b[t];
#pragma unroll
    for (int k = 0; k < 64; k++) acc += gs[k] * L1w[t * 64 + k];
    t1[t] = fmaxf(acc, 0.0f);
    __syncthreads();
    if (t < 10) {
        float a = L2b[t];
#pragma unroll
        for (int k = 0; k < 64; k++) a += t1[k] * L2w[t * 64 + k];
        out[gi * 10 + t] = a;
    }
}

// ------------------------------- launcher ----------------------------------

extern "C" void kernel_launch(void* const* d_in, const int* in_sizes, int n_in,
                              void* d_out, int out_size) {
    const float* x     = (const float*)d_in[0];
    const int*   ei    = (const int*)d_in[1];
    const int*   batch = (const int*)d_in[2];
    const float* W1 = (const float*)d_in[4];
    const float* b1 = (const float*)d_in[5];
    const float* W2 = (const float*)d_in[6];
    const float* b2 = (const float*)d_in[7];
    const float* W3 = (const float*)d_in[8];
    const float* b3 = (const float*)d_in[9];
    const float* W4 = (const float*)d_in[10];
    const float* b4 = (const float*)d_in[11];
    const float* L1w = (const float*)d_in[12];
    const float* L1b = (const float*)d_in[13];
    const float* L2w = (const float*)d_in[14];
    const float* L2b = (const float*)d_in[15];
    float* out = (float*)d_out;

    const int n = in_sizes[0] / 3;
    const int e = in_sizes[1] / 2;
    const int G = out_size / 10;

    const int* row = ei;
    const int* col = ei + e;

    uint2* hA; cudaGetSymbolAddress((void**)&hA, g_hA);
    uint2* hB; cudaGetSymbolAddress((void**)&hB, g_hB);
    float* bufA; cudaGetSymbolAddress((void**)&bufA, g_bufA);

    // ---- CSR build + prep ----
    {
        int tot = (n > G * 64) ? n : G * 64;
        init_kernel<<<(tot + 255) / 256, 256>>>(n, G * 64);
        hist_kernel<<<(e + 255) / 256, 256>>>(col, e);
        int nblk = (n + 511) / 512;
        scan_local<<<nblk, 256>>>(n);
        scan_spine<<<1, 256>>>(nblk);
        scan_add<<<(n + 255) / 256, 256>>>(n, e);
        fill_kernel<<<(e + 255) / 256, 256>>>(row, col, e);
        dinv_prep_kernel<<<(n + 255) / 256, 256>>>(x, n);
    }

    const int agg_grid = (n + 7) / 8;   // 8 warps/block, warp per node

    // ---- fused layers: gather(Cin, fp16) -> W -> relu -> (dinv-prescale) ----
    layer1_kernel<<<agg_grid, 256>>>(W1, b1, n);                                   // 3->16 (out hA)
    layer_kernel<16, 32, true , true ><<<agg_grid, 256>>>(hA, (__half*)hB, nullptr, W2, b2, n); // 16->32
    layer_kernel<32, 48, true , true ><<<agg_grid, 256>>>(hB, (__half*)hA, nullptr, W3, b3, n); // 32->48
    layer_kernel<48, 64, false, false><<<agg_grid, 256>>>(hA, nullptr, bufA, W4, b4, n);        // 48->64

    // ---- pool + MLP ----
    pool_kernel<<<(n + 511) / 512, 64>>>(bufA, batch, n);
    mlp_kernel<<<G, 64>>>(L1w, L1b, L2w, L2b, out);
}

// round 4
// speedup vs baseline: 1.9343x; 1.0726x over previous
#include <cuda_runtime.h>
#include <cuda_fp16.h>
#include <cuda_bf16.h>

// ---------------------------------------------------------------------------
// GNN: 4x GCNConv (3->16->32->48->64, relu) + global max pool + 2-layer MLP
// Round-4: unroll-4 gathers (MLP=4 on L2-hit latency), int2 histogram,
// offset-seeded cursors (1 atomic + 0 extra reads per edge in fill),
// 128B-padded 48ch rows, fp16 final features + half2 max-pool.
// ---------------------------------------------------------------------------

#define N_MAX 131072
#define E_MAX 3400000
#define G_MAX 512

__device__ int    g_deg[N_MAX];
__device__ int    g_cursor[N_MAX];        // seeded with offsets by scan_add
__device__ int    g_off[N_MAX + 1];
__device__ int    g_src[E_MAX];
__device__ int    g_bsum[256];
__device__ int    g_boff[256];
__device__ float  g_dinv[N_MAX];
__device__ uint2  g_s0[N_MAX];            // layer-1 input as half4, dinv-scaled
__device__ uint2  g_hA[N_MAX * 16];       // half feature buffer (<=64 ch, padded)
__device__ uint2  g_hB[N_MAX * 16];       // half feature buffer
__device__ float  g_pool[G_MAX * 64];

// ---------------------------- CSR construction ----------------------------

__global__ void init_kernel(int n, int gtot) {
    int i = blockIdx.x * blockDim.x + threadIdx.x;
    int tot = (n > gtot) ? n : gtot;
    for (; i < tot; i += gridDim.x * blockDim.x) {
        if (i < n) g_deg[i] = 0;
        if (i < gtot) g_pool[i] = 0.0f;   // relu outputs >= 0 -> 0 is max-identity
    }
}

__global__ void hist_kernel(const int* __restrict__ col, int e) {
    int i = blockIdx.x * blockDim.x + threadIdx.x;
    int e2 = e >> 1;
    if (i < e2) {
        int2 c = reinterpret_cast<const int2*>(col)[i];
        atomicAdd(&g_deg[c.x], 1);
        atomicAdd(&g_deg[c.y], 1);
    }
    if (i == 0 && (e & 1)) atomicAdd(&g_deg[col[e - 1]], 1);
}

// two-level exclusive scan of g_deg -> g_off (and g_cursor)
__global__ void scan_local(int n) {
    __shared__ int sm[256];
    int b = blockIdx.x, t = threadIdx.x;
    int i0 = b * 512 + 2 * t, i1 = i0 + 1;
    int v0 = (i0 < n) ? g_deg[i0] : 0;
    int v1 = (i1 < n) ? g_deg[i1] : 0;
    sm[t] = v0 + v1;
    __syncthreads();
    for (int o = 1; o < 256; o <<= 1) {
        int x = (t >= o) ? sm[t - o] : 0;
        __syncthreads();
        sm[t] += x;
        __syncthreads();
    }
    int ex = (t > 0) ? sm[t - 1] : 0;
    if (i0 < n) g_off[i0] = ex;
    if (i1 < n) g_off[i1] = ex + v0;
    if (t == 255) g_bsum[b] = sm[255];
}

__global__ void scan_spine(int nblk) {
    __shared__ int sm[256];
    int t = threadIdx.x;
    sm[t] = (t < nblk) ? g_bsum[t] : 0;
    __syncthreads();
    for (int o = 1; o < 256; o <<= 1) {
        int x = (t >= o) ? sm[t - o] : 0;
        __syncthreads();
        sm[t] += x;
        __syncthreads();
    }
    g_boff[t] = (t > 0) ? sm[t - 1] : 0;
}

__global__ void scan_add(int n, int e) {
    int i = blockIdx.x * blockDim.x + threadIdx.x;
    if (i < n) {
        int o = g_off[i] + g_boff[i >> 9];
        g_off[i] = o;
        g_cursor[i] = o;          // seed cursor = offset
    }
    if (i == 0) g_off[n] = e;
}

__global__ void fill_kernel(const int* __restrict__ row, const int* __restrict__ col, int e) {
    int i = blockIdx.x * blockDim.x + threadIdx.x;
    if (i < e) {
        int p = atomicAdd(&g_cursor[col[i]], 1);
        g_src[p] = row[i];
    }
}

// dinv + build dinv-scaled half4 layer-1 input
__global__ void dinv_prep_kernel(const float* __restrict__ x, int n) {
    int i = blockIdx.x * blockDim.x + threadIdx.x;
    if (i < n) {
        float dv = rsqrtf((float)(g_deg[i] + 1));  // +1 self loop
        g_dinv[i] = dv;
        __half2 lo = __floats2half2_rn(dv * x[3*i],   dv * x[3*i+1]);
        __half2 hi = __floats2half2_rn(dv * x[3*i+2], 0.0f);
        uint2 w;
        w.x = *reinterpret_cast<unsigned*>(&lo);
        w.y = *reinterpret_cast<unsigned*>(&hi);
        g_s0[i] = w;
    }
}

// ------------------------------- GCN layers -------------------------------

__device__ __forceinline__ void acc_half4(float& a0, float& a1, float& a2, float& a3, uint2 w) {
    float2 f0 = __half22float2(*reinterpret_cast<__half2*>(&w.x));
    float2 f1 = __half22float2(*reinterpret_cast<__half2*>(&w.y));
    a0 += f0.x; a1 += f0.y; a2 += f1.x; a3 += f1.y;
}

// Layer 1 (Cin=3 pad 4 -> Cout=16): edge-parallel half4 gather, shfl reduce.
__global__ void layer1_kernel(const float* __restrict__ W, const float* __restrict__ b,
                              int n) {
    __shared__ float Ws[48];
    __shared__ float bs[16];
    if (threadIdx.x < 48) Ws[threadIdx.x] = W[threadIdx.x];
    if (threadIdx.x < 16) bs[threadIdx.x] = b[threadIdx.x];
    __syncthreads();
    int warp = threadIdx.x >> 5, lane = threadIdx.x & 31;
    int v = blockIdx.x * 8 + warp;
    if (v >= n) return;
    float ax = 0.0f, ay = 0.0f, az = 0.0f, aw = 0.0f;
    const int jend = g_off[v + 1];
    int j = g_off[v] + lane;
    for (; j + 32 < jend; j += 64) {
        int u0 = __ldg(&g_src[j]);
        int u1 = __ldg(&g_src[j + 32]);
        acc_half4(ax, ay, az, aw, g_s0[u0]);
        acc_half4(ax, ay, az, aw, g_s0[u1]);
    }
    if (j < jend) acc_half4(ax, ay, az, aw, g_s0[__ldg(&g_src[j])]);
    if (lane == 0) acc_half4(ax, ay, az, aw, g_s0[v]);   // self loop
#pragma unroll
    for (int o = 16; o; o >>= 1) {
        ax += __shfl_xor_sync(0xffffffffu, ax, o);
        ay += __shfl_xor_sync(0xffffffffu, ay, o);
        az += __shfl_xor_sync(0xffffffffu, az, o);
    }
    float dv = g_dinv[v];
    ax *= dv; ay *= dv; az *= dv;
    if (lane < 16) {
        float r = bs[lane] + ax * Ws[lane*3] + ay * Ws[lane*3+1] + az * Ws[lane*3+2];
        __half* outh = reinterpret_cast<__half*>(g_hA);
        outh[v * 16 + lane] = __float2half_rn(dv * fmaxf(r, 0.0f));  // pre-scale
    }
}

// Layers 2-4: edge-group half4 gather (unroll 4) + shared-mem matmul.
// QC = CIN/4 lanes per edge row, EG edge groups per warp.
// IS = input row stride in uint2, OS = output row stride in halfs.
template <int CIN, int COUT, int IS, int OS, bool SCALE, bool HALFOUT>
__global__ void layer_kernel(const uint2* __restrict__ s, __half* __restrict__ outh,
                             float* __restrict__ outf,
                             const float* __restrict__ W, const float* __restrict__ b,
                             int n) {
    constexpr int QC = CIN / 4;
    constexpr int EG = 32 / QC;
    constexpr int ACT = QC * EG;
    __shared__ float Wt[CIN * COUT];     // transposed: Wt[k*COUT + c]
    __shared__ float bs[COUT];
    __shared__ float aggS[8][CIN];
    for (int i = threadIdx.x; i < CIN * COUT; i += blockDim.x) {
        int c = i / CIN, k = i - c * CIN;
        Wt[k * COUT + c] = W[i];
    }
    if (threadIdx.x < COUT) bs[threadIdx.x] = b[threadIdx.x];
    __syncthreads();
    int warp = threadIdx.x >> 5, lane = threadIdx.x & 31;
    int v = blockIdx.x * 8 + warp;
    if (v >= n) return;
    const float dv = g_dinv[v];
    const int eg = lane / QC;
    const int q  = lane - eg * QC;

    float a0 = 0.0f, a1 = 0.0f, a2 = 0.0f, a3 = 0.0f;
    const int jend = g_off[v + 1];
    int j = (lane < ACT) ? (g_off[v] + eg) : jend;
    if (lane < ACT && eg == 0)
        acc_half4(a0, a1, a2, a3, s[v * IS + q]);       // self loop
    for (; j + 3 * EG < jend; j += 4 * EG) {
        int u0 = __ldg(&g_src[j]);
        int u1 = __ldg(&g_src[j + EG]);
        int u2 = __ldg(&g_src[j + 2 * EG]);
        int u3 = __ldg(&g_src[j + 3 * EG]);
        uint2 w0 = s[u0 * IS + q];
        uint2 w1 = s[u1 * IS + q];
        uint2 w2 = s[u2 * IS + q];
        uint2 w3 = s[u3 * IS + q];
        acc_half4(a0, a1, a2, a3, w0);
        acc_half4(a0, a1, a2, a3, w1);
        acc_half4(a0, a1, a2, a3, w2);
        acc_half4(a0, a1, a2, a3, w3);
    }
    for (; j < jend; j += EG)
        acc_half4(a0, a1, a2, a3, s[__ldg(&g_src[j]) * IS + q]);
    // reduce across edge groups
    if constexpr ((QC & (QC - 1)) == 0) {
#pragma unroll
        for (int o = QC; o < 32; o <<= 1) {
            a0 += __shfl_xor_sync(0xffffffffu, a0, o);
            a1 += __shfl_xor_sync(0xffffffffu, a1, o);
            a2 += __shfl_xor_sync(0xffffffffu, a2, o);
            a3 += __shfl_xor_sync(0xffffffffu, a3, o);
        }
    } else {   // QC=12, EG=2
        a0 += __shfl_down_sync(0xffffffffu, a0, 12);
        a1 += __shfl_down_sync(0xffffffffu, a1, 12);
        a2 += __shfl_down_sync(0xffffffffu, a2, 12);
        a3 += __shfl_down_sync(0xffffffffu, a3, 12);
    }
    if (lane < QC) {
        aggS[warp][q * 4 + 0] = a0 * dv;
        aggS[warp][q * 4 + 1] = a1 * dv;
        aggS[warp][q * 4 + 2] = a2 * dv;
        aggS[warp][q * 4 + 3] = a3 * dv;
    }
    __syncwarp();
    float r0 = bs[lane];
    float r1 = (COUT > 32 && lane + 32 < COUT) ? bs[lane + 32] : 0.0f;
#pragma unroll
    for (int k = 0; k < CIN; k++) {
        float av = aggS[warp][k];                    // broadcast
        r0 += av * Wt[k * COUT + lane];
        if (COUT > 32 && lane + 32 < COUT) r1 += av * Wt[k * COUT + lane + 32];
    }
    r0 = fmaxf(r0, 0.0f);
    if (SCALE) r0 *= dv;
    if (HALFOUT) outh[v * OS + lane] = __float2half_rn(r0);
    else         outf[v * OS + lane] = r0;
    if (COUT > 32 && lane + 32 < COUT) {
        r1 = fmaxf(r1, 0.0f);
        if (SCALE) r1 *= dv;
        if (HALFOUT) outh[v * OS + lane + 32] = __float2half_rn(r1);
        else         outf[v * OS + lane + 32] = r1;
    }
}

// --------------------------- pool + final MLP ------------------------------

__device__ __forceinline__ void pool_flush(int cur, int c, __half2 m) {
    float2 f = __half22float2(m);
    atomicMax((int*)&g_pool[cur * 64 + 2 * c],     __float_as_int(f.x));
    atomicMax((int*)&g_pool[cur * 64 + 2 * c + 1], __float_as_int(f.y));
}

__global__ void pool_kernel(const __half2* __restrict__ h2, const int* __restrict__ batch, int n) {
    const int NPB = 256;
    int c = threadIdx.x;   // 32 threads = 32 half2 channel pairs
    int start = blockIdx.x * NPB;
    if (start >= n) return;
    int end = start + NPB; if (end > n) end = n;
    int cur = batch[start];
    __half2 m = __float2half2_rn(0.0f);
    for (int v = start; v < end; v++) {
        int gi = batch[v];
        if (gi != cur) {
            pool_flush(cur, c, m);
            cur = gi;
            m = __float2half2_rn(0.0f);
        }
        m = __hmax2(m, h2[v * 32 + c]);
    }
    pool_flush(cur, c, m);
}

__global__ void mlp_kernel(const float* __restrict__ L1w, const float* __restrict__ L1b,
                           const float* __restrict__ L2w, const float* __restrict__ L2b,
                           float* __restrict__ out) {
    __shared__ float gs[64];
    __shared__ float t1[64];
    int gi = blockIdx.x;
    int t = threadIdx.x;   // 64 threads
    gs[t] = g_pool[gi * 64 + t];
    __syncthreads();
    float acc = L1b[t];
#pragma unroll
    for (int k = 0; k < 64; k++) acc += gs[k] * L1w[t * 64 + k];
    t1[t] = fmaxf(acc, 0.0f);
    __syncthreads();
    if (t < 10) {
        float a = L2b[t];
#pragma unroll
        for (int k = 0; k < 64; k++) a += t1[k] * L2w[t * 64 + k];
        out[gi * 10 + t] = a;
    }
}

// ------------------------------- launcher ----------------------------------

extern "C" void kernel_launch(void* const* d_in, const int* in_sizes, int n_in,
                              void* d_out, int out_size) {
    const float* x     = (const float*)d_in[0];
    const int*   ei    = (const int*)d_in[1];
    const int*   batch = (const int*)d_in[2];
    const float* W1 = (const float*)d_in[4];
    const float* b1 = (const float*)d_in[5];
    const float* W2 = (const float*)d_in[6];
    const float* b2 = (const float*)d_in[7];
    const float* W3 = (const float*)d_in[8];
    const float* b3 = (const float*)d_in[9];
    const float* W4 = (const float*)d_in[10];
    const float* b4 = (const float*)d_in[11];
    const float* L1w = (const float*)d_in[12];
    const float* L1b = (const float*)d_in[13];
    const float* L2w = (const float*)d_in[14];
    const float* L2b = (const float*)d_in[15];
    float* out = (float*)d_out;

    const int n = in_sizes[0] / 3;
    const int e = in_sizes[1] / 2;
    const int G = out_size / 10;

    const int* row = ei;
    const int* col = ei + e;

    uint2* hA; cudaGetSymbolAddress((void**)&hA, g_hA);
    uint2* hB; cudaGetSymbolAddress((void**)&hB, g_hB);

    // ---- CSR build + prep ----
    {
        int tot = (n > G * 64) ? n : G * 64;
        init_kernel<<<(tot + 255) / 256, 256>>>(n, G * 64);
        hist_kernel<<<((e >> 1) + 255) / 256, 256>>>(col, e);
        int nblk = (n + 511) / 512;
        scan_local<<<nblk, 256>>>(n);
        scan_spine<<<1, 256>>>(nblk);
        scan_add<<<(n + 255) / 256, 256>>>(n, e);
        fill_kernel<<<(e + 255) / 256, 256>>>(row, col, e);
        dinv_prep_kernel<<<(n + 255) / 256, 256>>>(x, n);
    }

    const int agg_grid = (n + 7) / 8;   // 8 warps/block, warp per node

    // ---- fused layers: gather(Cin, fp16) -> W -> relu -> (dinv-prescale) ----
    layer1_kernel<<<agg_grid, 256>>>(W1, b1, n);                                    // 3->16 -> hA
    layer_kernel<16, 32, 4,  32, true , true ><<<agg_grid, 256>>>(hA, (__half*)hB, nullptr, W2, b2, n); // 16->32 -> hB
    layer_kernel<32, 48, 8,  64, true , true ><<<agg_grid, 256>>>(hB, (__half*)hA, nullptr, W3, b3, n); // 32->48 -> hA (128B rows)
    layer_kernel<48, 64, 16, 64, false, true ><<<agg_grid, 256>>>(hA, (__half*)hB, nullptr, W4, b4, n); // 48->64 -> hB (fp16)

    // ---- pool + MLP ----
    pool_kernel<<<(n + 255) / 256, 32>>>((const __half2*)hB, batch, n);
    mlp_kernel<<<G, 64>>>(L1w, L1b, L2w, L2b, out);
}